// round 13
// baseline (speedup 1.0000x reference)
#include <cuda_runtime.h>
#include <stdint.h>
#include <math.h>

// TopkMoeFFN: N=131072, H=128, O=128, E=8, top2, fp32.
// zero -> gate (atomic slot alloc) -> ffn x2 phases.
// k_ffn: 128x128x128 tiles, warp=32x64, A fragments built in registers
// straight from global x (no A smem), W-only smem (~72KB, 2 CTAs/SM),
// barriers only on expert change.

#define NTOK  131072
#define HDIM  128
#define ODIM  128
#define NEXP  8
#define NBLK  1024
#define GRID3 304
#define WPITCH 272

__device__ float4 g_meta[NTOK];
__device__ int g_cnt[2][NEXP];
__device__ unsigned int g_etok[2][NEXP * NTOK];
__device__ float g_egat[2][NEXP * NTOK];

__device__ __forceinline__ uint32_t smem_u32(const void* p) {
    uint32_t a;
    asm("{ .reg .u64 t; cvta.to.shared.u64 t, %1; cvt.u32.u64 %0, t; }"
        : "=r"(a) : "l"(p));
    return a;
}

__device__ __forceinline__ uint32_t cvt_bf16x2(float hi, float lo) {
    uint32_t d;
    asm("cvt.rn.bf16x2.f32 %0, %1, %2;" : "=r"(d) : "f"(hi), "f"(lo));
    return d;
}

__device__ __forceinline__ void split2(float f0, float f1,
                                       uint32_t& hi, uint32_t& lo) {
    hi = cvt_bf16x2(f1, f0);
    float h0 = __uint_as_float(hi << 16);
    float h1 = __uint_as_float(hi & 0xffff0000u);
    lo = cvt_bf16x2(f1 - h1, f0 - h0);
}

__device__ __forceinline__ void ldsm_x2t(uint32_t& r0, uint32_t& r1, uint32_t a) {
    asm volatile("ldmatrix.sync.aligned.m8n8.x2.trans.shared.b16 {%0,%1}, [%2];"
                 : "=r"(r0), "=r"(r1) : "r"(a));
}

__device__ __forceinline__ void mma16816(float* c,
                                         uint32_t a0, uint32_t a1, uint32_t a2,
                                         uint32_t a3, uint32_t b0, uint32_t b1) {
    asm volatile(
        "mma.sync.aligned.m16n8k16.row.col.f32.bf16.bf16.f32 "
        "{%0,%1,%2,%3}, {%4,%5,%6,%7}, {%8,%9}, {%0,%1,%2,%3};"
        : "+f"(c[0]), "+f"(c[1]), "+f"(c[2]), "+f"(c[3])
        : "r"(a0), "r"(a1), "r"(a2), "r"(a3), "r"(b0), "r"(b1));
}

// ---------------- kernel 0: zero counters (graph replays!) ----------------
__global__ void k_zero() {
    if (threadIdx.x < 16) ((int*)g_cnt)[threadIdx.x] = 0;
}

// ---------------- kernel 1: gating + atomic slot allocation ----------------
#define G_SX   0
#define G_SWG  (128 * 132 * 4)
#define G_SMEM (G_SWG + HDIM * NEXP * 4)

extern __shared__ char smraw[];

__global__ void __launch_bounds__(128)
k_gate(const float* __restrict__ x, const float* __restrict__ wg) {
    float* sx  = (float*)(smraw + G_SX);
    float* swg = (float*)(smraw + G_SWG);
    __shared__ int wh0[4][8], wh1[4][8];
    __shared__ int gb0[8], gb1[8];

    const int tid = threadIdx.x, lane = tid & 31, w = tid >> 5;
    const int blk = blockIdx.x, tok0 = blk * 128;

    for (int i = tid; i < HDIM * NEXP; i += 128) swg[i] = wg[i];
    const float4* xg = (const float4*)(x + (size_t)tok0 * HDIM);
    for (int i = tid; i < 128 * 32; i += 128) {
        float4 v = xg[i];
        int t = i >> 5, c = (i & 31) * 4;
        *(float4*)(sx + t * 132 + c) = v;
    }
    __syncthreads();

    float lg[NEXP];
#pragma unroll
    for (int e = 0; e < NEXP; e++) lg[e] = 0.f;
    const float* xr = sx + tid * 132;
#pragma unroll 4
    for (int h4 = 0; h4 < 32; h4++) {
        float4 xq = *(const float4*)(xr + h4 * 4);
        const float* wr = swg + h4 * 32;
#pragma unroll
        for (int j = 0; j < 4; j++) {
            float xv = (j == 0) ? xq.x : (j == 1) ? xq.y : (j == 2) ? xq.z : xq.w;
            float4 wa = *(const float4*)(wr + j * 8);
            float4 wb = *(const float4*)(wr + j * 8 + 4);
            lg[0] = fmaf(xv, wa.x, lg[0]); lg[1] = fmaf(xv, wa.y, lg[1]);
            lg[2] = fmaf(xv, wa.z, lg[2]); lg[3] = fmaf(xv, wa.w, lg[3]);
            lg[4] = fmaf(xv, wb.x, lg[4]); lg[5] = fmaf(xv, wb.y, lg[5]);
            lg[6] = fmaf(xv, wb.z, lg[6]); lg[7] = fmaf(xv, wb.w, lg[7]);
        }
    }
    int i0 = 0; float v0 = lg[0];
#pragma unroll
    for (int e = 1; e < NEXP; e++)
        if (lg[e] > v0) { v0 = lg[e]; i0 = e; }
    int i1 = -1; float v1 = -3.4e38f;
#pragma unroll
    for (int e = 0; e < NEXP; e++)
        if (e != i0 && lg[e] > v1) { v1 = lg[e]; i1 = e; }
    float e1 = expf(v1 - v0);
    float g0 = 1.f / (1.f + e1);
    float g1 = e1 * g0;

    unsigned ltm = (1u << lane) - 1u;
    int myr0 = 0, myr1 = 0;
#pragma unroll
    for (int e = 0; e < NEXP; e++) {
        unsigned m0 = __ballot_sync(0xffffffffu, i0 == e);
        unsigned m1 = __ballot_sync(0xffffffffu, i1 == e);
        if (i0 == e) myr0 = __popc(m0 & ltm);
        if (i1 == e) myr1 = __popc(m1 & ltm);
        if (lane == e) { wh0[w][e] = __popc(m0); wh1[w][e] = __popc(m1); }
    }
    __syncthreads();
    int r0 = myr0, r1 = myr1;
    for (int ww = 0; ww < w; ww++) { r0 += wh0[ww][i0]; r1 += wh1[ww][i1]; }

    if (tid < NEXP) {
        int c0 = wh0[0][tid] + wh0[1][tid] + wh0[2][tid] + wh0[3][tid];
        int c1 = wh1[0][tid] + wh1[1][tid] + wh1[2][tid] + wh1[3][tid];
        gb0[tid] = atomicAdd(&g_cnt[0][tid], c0);
        gb1[tid] = atomicAdd(&g_cnt[1][tid], c1);
    }
    __syncthreads();

    int token = tok0 + tid;
    int s0 = gb0[i0] + r0, s1 = gb1[i1] + r1;
    g_etok[0][i0 * NTOK + s0] = (unsigned)token;
    g_egat[0][i0 * NTOK + s0] = g0;
    g_etok[1][i1 * NTOK + s1] = (unsigned)token;
    g_egat[1][i1 * NTOK + s1] = g1;
    g_meta[token] = make_float4(
        __uint_as_float((unsigned)i0 | ((unsigned)i1 << 8)), g0, g1, 0.f);
}

// ---------------- kernel 2: FFN GEMM, A-from-global, 2 CTAs/SM ----------------
#define F_WHI   0
#define F_WLO   34816
#define F_BIAS  69632
#define F_SMEM  73856
#define NTHR_F 256

#define TILE_ELI(t, e_, li_) do { \
        e_ = 0; \
        _Pragma("unroll") \
        for (int k_ = 0; k_ < NEXP; k_++) if (tb[k_ + 1] <= (t)) e_ = k_ + 1; \
        li_ = (t) - tb[e_]; \
    } while (0)

__global__ void __launch_bounds__(NTHR_F, 2)
k_ffn(const float* __restrict__ x, const float* __restrict__ we,
      const float* __restrict__ be, float* __restrict__ out, int p) {
    const int tid = threadIdx.x, lane = tid & 31, w = tid >> 5;
    float* sbias = (float*)(smraw + F_BIAS);
    const uint32_t su = smem_u32(smraw);

    const unsigned* tokl = g_etok[p];
    const float* gatel   = g_egat[p];

    int cnt[NEXP], tb[NEXP + 1];
    tb[0] = 0;
#pragma unroll
    for (int e = 0; e < NEXP; e++) {
        cnt[e] = g_cnt[p][e];
        tb[e + 1] = tb[e] + ((cnt[e] + 127) >> 7);
    }
    const int ntiles = tb[NEXP];
    const int t0 = (int)((long long)blockIdx.x * ntiles / GRID3);
    const int t1 = (int)((long long)(blockIdx.x + 1) * ntiles / GRID3);
    if (t0 >= t1) return;

    for (int i = tid; i < NEXP * ODIM; i += NTHR_F) sbias[i] = be[i];

    // warp job: rows [mt*32, +32), cols [nh*64, +64)
    const int mt = w >> 1, nh = w & 1;
    const int qr = lane >> 2, qk = (lane & 3) * 2;
    const uint32_t b_base = su + F_WHI + (uint32_t)(lane & 15) * WPITCH
                          + (uint32_t)nh * 128u;

    int cur_e = -1;
    for (int t = t0; t < t1; t++) {
        int e, li;
        TILE_ELI(t, e, li);
        const int valid = min(128, cnt[e] - li * 128);
        const int lb = e * NTOK + li * 128;

        // per-lane rows/tokens/gates (registers only; no shared tile state)
        int r00 = mt * 32 + qr, r01 = r00 + 8, r10 = r00 + 16, r11 = r00 + 24;
        int s00 = r00 < valid ? r00 : 0, s01 = r01 < valid ? r01 : 0;
        int s10 = r10 < valid ? r10 : 0, s11 = r11 < valid ? r11 : 0;
        unsigned tk00 = tokl[lb + s00], tk01 = tokl[lb + s01];
        unsigned tk10 = tokl[lb + s10], tk11 = tokl[lb + s11];
        float g00 = r00 < valid ? gatel[lb + s00] : 0.f;
        float g01 = r01 < valid ? gatel[lb + s01] : 0.f;
        float g10 = r10 < valid ? gatel[lb + s10] : 0.f;
        float g11 = r11 < valid ? gatel[lb + s11] : 0.f;

        const float* xb00 = x + (size_t)tk00 * HDIM + qk;
        const float* xb01 = x + (size_t)tk01 * HDIM + qk;
        const float* xb10 = x + (size_t)tk10 * HDIM + qk;
        const float* xb11 = x + (size_t)tk11 * HDIM + qk;

        // W stage only on expert change (the ONLY barriers in the loop)
        if (e != cur_e) {
            __syncthreads();
            const float4* wgl = (const float4*)(we + (size_t)e * HDIM * ODIM);
#pragma unroll
            for (int i2 = 0; i2 < 16; i2++) {
                int i = tid + i2 * NTHR_F;
                float4 v = wgl[i];
                int h = i >> 5, o4 = i & 31;
                uint32_t h0, l0, h1, l1;
                split2(v.x, v.y, h0, l0);
                split2(v.z, v.w, h1, l1);
                uint32_t off = (uint32_t)h * WPITCH + (uint32_t)o4 * 8;
                *(uint2*)(smraw + F_WHI + off) = make_uint2(h0, h1);
                *(uint2*)(smraw + F_WLO + off) = make_uint2(l0, l1);
            }
            cur_e = e;
            __syncthreads();
        }

        float acc[2][8][4];
#pragma unroll
        for (int m = 0; m < 2; m++)
#pragma unroll
            for (int nt = 0; nt < 8; nt++)
#pragma unroll
                for (int j = 0; j < 4; j++) acc[m][nt][j] = 0.f;

#pragma unroll
        for (int kb = 0; kb < 8; kb++) {
            const int ko = kb * 16;
            // A fragments straight from global x (quad-coalesced LDG.64)
            float2 c00 = *(const float2*)(xb00 + ko);
            float2 c01 = *(const float2*)(xb01 + ko);
            float2 c02 = *(const float2*)(xb00 + ko + 8);
            float2 c03 = *(const float2*)(xb01 + ko + 8);
            float2 c10 = *(const float2*)(xb10 + ko);
            float2 c11 = *(const float2*)(xb11 + ko);
            float2 c12 = *(const float2*)(xb10 + ko + 8);
            float2 c13 = *(const float2*)(xb11 + ko + 8);

            uint32_t ah[2][4], al[2][4];
            split2(g00 * c00.x, g00 * c00.y, ah[0][0], al[0][0]);
            split2(g01 * c01.x, g01 * c01.y, ah[0][1], al[0][1]);
            split2(g00 * c02.x, g00 * c02.y, ah[0][2], al[0][2]);
            split2(g01 * c03.x, g01 * c03.y, ah[0][3], al[0][3]);
            split2(g10 * c10.x, g10 * c10.y, ah[1][0], al[1][0]);
            split2(g11 * c11.x, g11 * c11.y, ah[1][1], al[1][1]);
            split2(g10 * c12.x, g10 * c12.y, ah[1][2], al[1][2]);
            split2(g11 * c13.x, g11 * c13.y, ah[1][3], al[1][3]);

            uint32_t bb = b_base + (uint32_t)kb * 16 * WPITCH;
#pragma unroll
            for (int nt = 0; nt < 8; nt++) {
                uint32_t bh0, bh1, bl0, bl1;
                ldsm_x2t(bh0, bh1, bb + nt * 16);
                ldsm_x2t(bl0, bl1, bb + nt * 16 + (F_WLO - F_WHI));
#pragma unroll
                for (int m = 0; m < 2; m++) {
                    mma16816(acc[m][nt], ah[m][0], ah[m][1], ah[m][2], ah[m][3],
                             bh0, bh1);
                    mma16816(acc[m][nt], ah[m][0], ah[m][1], ah[m][2], ah[m][3],
                             bl0, bl1);
                    mma16816(acc[m][nt], al[m][0], al[m][1], al[m][2], al[m][3],
                             bh0, bh1);
                }
            }
        }

        // epilogue (tokens/gates already in registers)
#pragma unroll
        for (int m = 0; m < 2; m++) {
            int ra = m ? r10 : r00;
            int rb = m ? r11 : r01;
            unsigned ta = m ? tk10 : tk00;
            unsigned tbk = m ? tk11 : tk01;
            bool va = ra < valid, vb = rb < valid;
            float* opa = out + (size_t)ta * ODIM;
            float* opb = out + (size_t)tbk * ODIM;
            if (p == 0) {
#pragma unroll
                for (int hrow = 0; hrow < 2; hrow++) {
                    if (!(hrow ? vb : va)) continue;
                    unsigned tk = hrow ? tbk : ta;
                    float* op = hrow ? opb : opa;
                    float4 mm = g_meta[tk];
                    unsigned u = __float_as_uint(mm.x);
                    const float* b0p = sbias + (u & 0xff) * ODIM;
                    const float* b1p = sbias + ((u >> 8) & 0xff) * ODIM;
                    float gg0 = mm.y, gg1 = mm.z;
                    const int ci = hrow * 2;
#pragma unroll
                    for (int nt = 0; nt < 8; nt++) {
                        int col = nh * 64 + nt * 8 + qk;
                        float2 v;
                        v.x = acc[m][nt][ci] + gg0 * b0p[col] + gg1 * b1p[col];
                        v.y = acc[m][nt][ci + 1]
                            + gg0 * b0p[col + 1] + gg1 * b1p[col + 1];
                        *(float2*)(op + col) = v;
                    }
                }
            } else {
                float2 o[2][8];
#pragma unroll
                for (int nt = 0; nt < 8; nt++) {
                    int col = nh * 64 + nt * 8 + qk;
                    if (va) o[0][nt] = *(float2*)(opa + col);
                    if (vb) o[1][nt] = *(float2*)(opb + col);
                }
#pragma unroll
                for (int nt = 0; nt < 8; nt++) {
                    int col = nh * 64 + nt * 8 + qk;
                    if (va) {
                        float2 v = o[0][nt];
                        v.x += acc[m][nt][0];
                        v.y += acc[m][nt][1];
                        *(float2*)(opa + col) = v;
                    }
                    if (vb) {
                        float2 v = o[1][nt];
                        v.x += acc[m][nt][2];
                        v.y += acc[m][nt][3];
                        *(float2*)(opb + col) = v;
                    }
                }
            }
        }
    }
}

// ---------------- launch ----------------
extern "C" void kernel_launch(void* const* d_in, const int* in_sizes, int n_in,
                              void* d_out, int out_size) {
    const float* x  = (const float*)d_in[0];
    const float* wg = (const float*)d_in[1];
    // d_in[2] = w_noise (inactive in eval mode)
    const float* we = (const float*)d_in[3];
    const float* be = (const float*)d_in[4];
    float* out = (float*)d_out;

    cudaFuncSetAttribute(k_gate, cudaFuncAttributeMaxDynamicSharedMemorySize,
                         G_SMEM);
    cudaFuncSetAttribute(k_ffn, cudaFuncAttributeMaxDynamicSharedMemorySize,
                         F_SMEM);

    k_zero<<<1, 32>>>();
    k_gate<<<NBLK, 128, G_SMEM>>>(x, wg);
    k_ffn<<<GRID3, NTHR_F, F_SMEM>>>(x, we, be, out, 0);
    k_ffn<<<GRID3, NTHR_F, F_SMEM>>>(x, we, be, out, 1);
}

// round 14
// speedup vs baseline: 1.3230x; 1.3230x over previous
#include <cuda_runtime.h>
#include <stdint.h>
#include <math.h>

// TopkMoeFFN: N=131072, H=128, O=128, E=8, top2, fp32.
// zero -> gate (atomic slot alloc + tf32-rounded x copy) -> ffn x2.
// k_ffn: single-pass TF32 mma (m16n8k8), A cp.async'd directly from
// pre-rounded g_xt (no convert/stage), W^T staged tf32-rounded in smem,
// gate applied in epilogue. Double-buffered A, 128x128x128 tiles.

#define NTOK  131072
#define HDIM  128
#define ODIM  128
#define NEXP  8
#define NBLK  1024
#define GRID3 152
#define FPITCH 132          // fp32 tile row pitch in floats (528B)

__device__ float4 g_meta[NTOK];
__device__ int g_cnt[2][NEXP];
__device__ unsigned int g_etok[2][NEXP * NTOK];
__device__ float g_egat[2][NEXP * NTOK];
__device__ uint32_t g_xt[NTOK * HDIM];   // tf32-rounded x (fp32 bits)

__device__ __forceinline__ uint32_t smem_u32(const void* p) {
    uint32_t a;
    asm("{ .reg .u64 t; cvta.to.shared.u64 t, %1; cvt.u32.u64 %0, t; }"
        : "=r"(a) : "l"(p));
    return a;
}

__device__ __forceinline__ uint32_t tf32rn(float f) {
    uint32_t r;
    asm("cvt.rna.tf32.f32 %0, %1;" : "=r"(r) : "f"(f));
    return r;
}

__device__ __forceinline__ void ldsm_x4(uint32_t& r0, uint32_t& r1,
                                        uint32_t& r2, uint32_t& r3, uint32_t a) {
    asm volatile("ldmatrix.sync.aligned.m8n8.x4.shared.b16 {%0,%1,%2,%3}, [%4];"
                 : "=r"(r0), "=r"(r1), "=r"(r2), "=r"(r3) : "r"(a));
}

__device__ __forceinline__ void mma_tf32(float* c,
                                         uint32_t a0, uint32_t a1, uint32_t a2,
                                         uint32_t a3, uint32_t b0, uint32_t b1) {
    asm volatile(
        "mma.sync.aligned.m16n8k8.row.col.f32.tf32.tf32.f32 "
        "{%0,%1,%2,%3}, {%4,%5,%6,%7}, {%8,%9}, {%0,%1,%2,%3};"
        : "+f"(c[0]), "+f"(c[1]), "+f"(c[2]), "+f"(c[3])
        : "r"(a0), "r"(a1), "r"(a2), "r"(a3), "r"(b0), "r"(b1));
}

__device__ __forceinline__ void cpa16(uint32_t dst, const void* src) {
    asm volatile("cp.async.cg.shared.global [%0], [%1], 16;"
                 :: "r"(dst), "l"(src) : "memory");
}

// ---------------- kernel 0: zero counters (graph replays!) ----------------
__global__ void k_zero() {
    if (threadIdx.x < 16) ((int*)g_cnt)[threadIdx.x] = 0;
}

// ---------------- kernel 1: gating + slot alloc + x tf32 copy ----------------
#define G_SX   0
#define G_SWG  (128 * 132 * 4)
#define G_SMEM (G_SWG + HDIM * NEXP * 4)

extern __shared__ char smraw[];

__global__ void __launch_bounds__(128)
k_gate(const float* __restrict__ x, const float* __restrict__ wg) {
    float* sx  = (float*)(smraw + G_SX);
    float* swg = (float*)(smraw + G_SWG);
    __shared__ int wh0[4][8], wh1[4][8];
    __shared__ int gb0[8], gb1[8];

    const int tid = threadIdx.x, lane = tid & 31, w = tid >> 5;
    const int blk = blockIdx.x, tok0 = blk * 128;

    for (int i = tid; i < HDIM * NEXP; i += 128) swg[i] = wg[i];
    const float4* xg = (const float4*)(x + (size_t)tok0 * HDIM);
    for (int i = tid; i < 128 * 32; i += 128) {
        float4 v = xg[i];
        int t = i >> 5, c = (i & 31) * 4;
        *(float4*)(sx + t * 132 + c) = v;
        // emit tf32-rounded copy (coalesced)
        uint4 tv = make_uint4(tf32rn(v.x), tf32rn(v.y), tf32rn(v.z), tf32rn(v.w));
        ((uint4*)g_xt)[(size_t)(tok0 + t) * 32 + (i & 31)] = tv;
    }
    __syncthreads();

    float lg[NEXP];
#pragma unroll
    for (int e = 0; e < NEXP; e++) lg[e] = 0.f;
    const float* xr = sx + tid * 132;
#pragma unroll 4
    for (int h4 = 0; h4 < 32; h4++) {
        float4 xq = *(const float4*)(xr + h4 * 4);
        const float* wr = swg + h4 * 32;
#pragma unroll
        for (int j = 0; j < 4; j++) {
            float xv = (j == 0) ? xq.x : (j == 1) ? xq.y : (j == 2) ? xq.z : xq.w;
            float4 wa = *(const float4*)(wr + j * 8);
            float4 wb = *(const float4*)(wr + j * 8 + 4);
            lg[0] = fmaf(xv, wa.x, lg[0]); lg[1] = fmaf(xv, wa.y, lg[1]);
            lg[2] = fmaf(xv, wa.z, lg[2]); lg[3] = fmaf(xv, wa.w, lg[3]);
            lg[4] = fmaf(xv, wb.x, lg[4]); lg[5] = fmaf(xv, wb.y, lg[5]);
            lg[6] = fmaf(xv, wb.z, lg[6]); lg[7] = fmaf(xv, wb.w, lg[7]);
        }
    }
    int i0 = 0; float v0 = lg[0];
#pragma unroll
    for (int e = 1; e < NEXP; e++)
        if (lg[e] > v0) { v0 = lg[e]; i0 = e; }
    int i1 = -1; float v1 = -3.4e38f;
#pragma unroll
    for (int e = 0; e < NEXP; e++)
        if (e != i0 && lg[e] > v1) { v1 = lg[e]; i1 = e; }
    float e1 = expf(v1 - v0);
    float g0 = 1.f / (1.f + e1);
    float g1 = e1 * g0;

    unsigned ltm = (1u << lane) - 1u;
    int myr0 = 0, myr1 = 0;
#pragma unroll
    for (int e = 0; e < NEXP; e++) {
        unsigned m0 = __ballot_sync(0xffffffffu, i0 == e);
        unsigned m1 = __ballot_sync(0xffffffffu, i1 == e);
        if (i0 == e) myr0 = __popc(m0 & ltm);
        if (i1 == e) myr1 = __popc(m1 & ltm);
        if (lane == e) { wh0[w][e] = __popc(m0); wh1[w][e] = __popc(m1); }
    }
    __syncthreads();
    int r0 = myr0, r1 = myr1;
    for (int ww = 0; ww < w; ww++) { r0 += wh0[ww][i0]; r1 += wh1[ww][i1]; }

    if (tid < NEXP) {
        int c0 = wh0[0][tid] + wh0[1][tid] + wh0[2][tid] + wh0[3][tid];
        int c1 = wh1[0][tid] + wh1[1][tid] + wh1[2][tid] + wh1[3][tid];
        gb0[tid] = atomicAdd(&g_cnt[0][tid], c0);
        gb1[tid] = atomicAdd(&g_cnt[1][tid], c1);
    }
    __syncthreads();

    int token = tok0 + tid;
    int s0 = gb0[i0] + r0, s1 = gb1[i1] + r1;
    g_etok[0][i0 * NTOK + s0] = (unsigned)token;
    g_egat[0][i0 * NTOK + s0] = g0;
    g_etok[1][i1 * NTOK + s1] = (unsigned)token;
    g_egat[1][i1 * NTOK + s1] = g1;
    g_meta[token] = make_float4(
        __uint_as_float((unsigned)i0 | ((unsigned)i1 << 8)), g0, g1, 0.f);
}

// ---------------- kernel 2: TF32 FFN GEMM ----------------
// smem: W^T [o=128][132f] | A0 [128][132f] | A1 | bias | tok/gate/meta x2
#define F_WT    0
#define F_A0    67584
#define F_A1    135168
#define F_BIAS  202752
#define F_TOK   206848      // 2 x 128 int
#define F_SGT   207872      // 2 x 128 float
#define F_META  208896      // 2 x 128 float4
#define F_SMEM  212992
#define NTHR_F 512

#define TILE_ELI(t, e_, li_) do { \
        e_ = 0; \
        _Pragma("unroll") \
        for (int k_ = 0; k_ < NEXP; k_++) if (tb[k_ + 1] <= (t)) e_ = k_ + 1; \
        li_ = (t) - tb[e_]; \
    } while (0)

__global__ void __launch_bounds__(NTHR_F, 1)
k_ffn(const float* __restrict__ we, const float* __restrict__ be,
      float* __restrict__ out, int p) {
    const int tid = threadIdx.x, lane = tid & 31, w = tid >> 5;
    float* sbias = (float*)(smraw + F_BIAS);
    int* stok = (int*)(smraw + F_TOK);
    float* sgt = (float*)(smraw + F_SGT);
    float4* smeta = (float4*)(smraw + F_META);
    const uint32_t su = smem_u32(smraw);

    const unsigned* tokl = g_etok[p];
    const float* gatel   = g_egat[p];

    int cnt[NEXP], tb[NEXP + 1];
    tb[0] = 0;
#pragma unroll
    for (int e = 0; e < NEXP; e++) {
        cnt[e] = g_cnt[p][e];
        tb[e + 1] = tb[e] + ((cnt[e] + 127) >> 7);
    }
    const int ntiles = tb[NEXP];
    const int t0 = (int)((long long)blockIdx.x * ntiles / GRID3);
    const int t1 = (int)((long long)(blockIdx.x + 1) * ntiles / GRID3);
    if (t0 >= t1) return;

    for (int i = tid; i < NEXP * ODIM; i += NTHR_F) sbias[i] = be[i];

    // warp job: rows [mt*32,+32), cols [nq*32,+32)
    const int mt = w >> 2, nq = w & 3;
    // A ldsm lane address (m16 x k8 tiles): row = mt*32 + (l&7) + ((l>>3)&1)*8
    const uint32_t a_loff = (uint32_t)(mt * 32 + (lane & 7) + ((lane >> 3) & 1) * 8)
                          * (FPITCH * 4) + (uint32_t)(lane >> 4) * 16u;
    // B ldsm lane address (n8 x k16 tiles): row = nq*32 + (l&7), tile -> k offset
    const uint32_t b_loff = su + F_WT
                          + (uint32_t)(nq * 32 + (lane & 7)) * (FPITCH * 4)
                          + (uint32_t)(lane >> 3) * 16u;

    const int row = tid >> 2, q = tid & 3;
    const uint32_t a_dst = (uint32_t)row * (FPITCH * 4) + (uint32_t)q * 128u;

    // prologue: token/gate(t0), cp.async A(t0) -> buf0
    unsigned nx_token; float nx_gate;
    {
        int e_, li_;
        TILE_ELI(t0, e_, li_);
        int lb = e_ * NTOK + li_ * 128;
        int v0 = min(128, cnt[e_] - li_ * 128);
        nx_token = 0; nx_gate = 0.f;
        if (row < v0) { nx_token = tokl[lb + row]; nx_gate = gatel[lb + row]; }
        const char* src = (const char*)(g_xt + (size_t)nx_token * HDIM + q * 32);
#pragma unroll
        for (int i = 0; i < 8; i++)
            cpa16(su + F_A0 + a_dst + i * 16, src + i * 16);
        asm volatile("cp.async.commit_group;" ::: "memory");
    }

    int cur_e = -1;
    for (int t = t0; t < t1; t++) {
        const int cb = (t - t0) & 1;
        int e, li;
        TILE_ELI(t, e, li);
        const int valid = min(128, cnt[e] - li * 128);
        const unsigned token = nx_token;
        const float gv = nx_gate;

        if (t + 1 < t1) {
            int en, lin;
            TILE_ELI(t + 1, en, lin);
            int lbn = en * NTOK + lin * 128;
            int vn = min(128, cnt[en] - lin * 128);
            nx_token = 0; nx_gate = 0.f;
            if (row < vn) { nx_token = tokl[lbn + row]; nx_gate = gatel[lbn + row]; }
        }

        __syncthreads();   // GEMM(t-1) done: other A buf + W writable

        // stage W^T tf32-rounded on expert change (transpose via regs)
        if (e != cur_e) {
            const float* wsrc = we + (size_t)e * HDIM * ODIM;
#pragma unroll
            for (int i2 = 0; i2 < 32; i2++) {
                int i = tid + i2 * NTHR_F;       // i = h*128 + o
                int h = i >> 7, o = i & 127;
                ((uint32_t*)smraw)[o * FPITCH + h] = tf32rn(wsrc[i]);
            }
            cur_e = e;
        }

        // prefetch A(t+1) into other buffer
        if (t + 1 < t1) {
            const uint32_t abuf = cb ? F_A0 : F_A1;
            const char* src = (const char*)(g_xt + (size_t)nx_token * HDIM + q * 32);
#pragma unroll
            for (int i = 0; i < 8; i++)
                cpa16(su + abuf + a_dst + i * 16, src + i * 16);
        }
        asm volatile("cp.async.commit_group;" ::: "memory");

        if (q == 0) {
            stok[cb * 128 + row] = (int)token;
            sgt[cb * 128 + row] = gv;
            if (p == 0) smeta[cb * 128 + row] = g_meta[token];
        }
        asm volatile("cp.async.wait_group 1;" ::: "memory");   // A(t) arrived
        __syncthreads();   // A(t) + W + tok visible

        // GEMM: 2 m16 x 4 n8 x 16 k8, TF32
        const uint32_t a_base = su + (cb ? F_A1 : F_A0) + a_loff;
        float acc[2][4][4];
#pragma unroll
        for (int m = 0; m < 2; m++)
#pragma unroll
            for (int nt = 0; nt < 4; nt++)
#pragma unroll
                for (int j = 0; j < 4; j++) acc[m][nt][j] = 0.f;

#pragma unroll
        for (int k2 = 0; k2 < 8; k2++) {       // k16 steps
            uint32_t a8[2][2][4];              // [m16][k8][4]
#pragma unroll
            for (int m = 0; m < 2; m++) {
                uint32_t ab = a_base + (uint32_t)m * 16 * (FPITCH * 4)
                            + (uint32_t)k2 * 64;
                ldsm_x4(a8[m][0][0], a8[m][0][1], a8[m][0][2], a8[m][0][3], ab);
                ldsm_x4(a8[m][1][0], a8[m][1][1], a8[m][1][2], a8[m][1][3],
                        ab + 32);
            }
            uint32_t bbv[4][4];                // [n8][b0lo,b1lo,b0hi,b1hi]
#pragma unroll
            for (int nt = 0; nt < 4; nt++) {
                uint32_t bb = b_loff + (uint32_t)nt * 8 * (FPITCH * 4)
                            + (uint32_t)k2 * 64;
                ldsm_x4(bbv[nt][0], bbv[nt][1], bbv[nt][2], bbv[nt][3], bb);
            }
#pragma unroll
            for (int kb = 0; kb < 2; kb++)
#pragma unroll
                for (int nt = 0; nt < 4; nt++)
#pragma unroll
                    for (int m = 0; m < 2; m++)
                        mma_tf32(acc[m][nt],
                                 a8[m][kb][0], a8[m][kb][1],
                                 a8[m][kb][2], a8[m][kb][3],
                                 bbv[nt][kb * 2], bbv[nt][kb * 2 + 1]);
        }

        // epilogue: gate applied here
        const int qr = lane >> 2, qk = (lane & 3) * 2;
#pragma unroll
        for (int m = 0; m < 2; m++) {
            int ra = mt * 32 + m * 16 + qr;
            int rb = ra + 8;
            bool va = ra < valid, vb = rb < valid;
            float* opa = va ? out + (size_t)stok[cb * 128 + ra] * ODIM : 0;
            float* opb = vb ? out + (size_t)stok[cb * 128 + rb] * ODIM : 0;
            float ga = va ? sgt[cb * 128 + ra] : 0.f;
            float gb = vb ? sgt[cb * 128 + rb] : 0.f;
            if (p == 0) {
#pragma unroll
                for (int hrow = 0; hrow < 2; hrow++) {
                    int r = hrow ? rb : ra;
                    float* op = hrow ? opb : opa;
                    float g = hrow ? gb : ga;
                    if (!(hrow ? vb : va)) continue;
                    float4 mm = smeta[cb * 128 + r];
                    unsigned u = __float_as_uint(mm.x);
                    const float* b0p = sbias + (u & 0xff) * ODIM;
                    const float* b1p = sbias + ((u >> 8) & 0xff) * ODIM;
                    float gg0 = mm.y, gg1 = mm.z;
                    const int ci = hrow * 2;
#pragma unroll
                    for (int nt = 0; nt < 4; nt++) {
                        int col = nq * 32 + nt * 8 + qk;
                        float2 v;
                        v.x = g * acc[m][nt][ci]
                            + gg0 * b0p[col] + gg1 * b1p[col];
                        v.y = g * acc[m][nt][ci + 1]
                            + gg0 * b0p[col + 1] + gg1 * b1p[col + 1];
                        *(float2*)(op + col) = v;
                    }
                }
            } else {
                float2 o[2][4];
#pragma unroll
                for (int nt = 0; nt < 4; nt++) {
                    int col = nq * 32 + nt * 8 + qk;
                    if (va) o[0][nt] = *(float2*)(opa + col);
                    if (vb) o[1][nt] = *(float2*)(opb + col);
                }
#pragma unroll
                for (int nt = 0; nt < 4; nt++) {
                    int col = nq * 32 + nt * 8 + qk;
                    if (va) {
                        float2 v = o[0][nt];
                        v.x += ga * acc[m][nt][0];
                        v.y += ga * acc[m][nt][1];
                        *(float2*)(opa + col) = v;
                    }
                    if (vb) {
                        float2 v = o[1][nt];
                        v.x += gb * acc[m][nt][2];
                        v.y += gb * acc[m][nt][3];
                        *(float2*)(opb + col) = v;
                    }
                }
            }
        }
    }
}

// ---------------- launch ----------------
extern "C" void kernel_launch(void* const* d_in, const int* in_sizes, int n_in,
                              void* d_out, int out_size) {
    const float* x  = (const float*)d_in[0];
    const float* wg = (const float*)d_in[1];
    // d_in[2] = w_noise (inactive in eval mode)
    const float* we = (const float*)d_in[3];
    const float* be = (const float*)d_in[4];
    float* out = (float*)d_out;

    cudaFuncSetAttribute(k_gate, cudaFuncAttributeMaxDynamicSharedMemorySize,
                         G_SMEM);
    cudaFuncSetAttribute(k_ffn, cudaFuncAttributeMaxDynamicSharedMemorySize,
                         F_SMEM);

    k_zero<<<1, 32>>>();
    k_gate<<<NBLK, 128, G_SMEM>>>(x, wg);
    k_ffn<<<GRID3, NTHR_F, F_SMEM>>>(we, be, out, 0);
    k_ffn<<<GRID3, NTHR_F, F_SMEM>>>(we, be, out, 1);
}

// round 15
// speedup vs baseline: 1.4425x; 1.0903x over previous
#include <cuda_runtime.h>
#include <stdint.h>
#include <math.h>

// TopkMoeFFN: N=131072, H=128, O=128, E=8, top2, fp32.
// zero -> gate (atomic slot alloc) -> ffn x2 phases.
// k_ffn: single-pass TF32 mma (m16n8k8). A cp.async'd raw from x,
// tf32-rounded (cvt.rna) on fragment registers post-ldmatrix; W^T staged
// tf32-rounded in smem. Gate applied in epilogue. Double-buffered A.

#define NTOK  131072
#define HDIM  128
#define ODIM  128
#define NEXP  8
#define NBLK  1024
#define GRID3 152
#define FPITCH 132          // fp32 tile row pitch in floats (528B)

__device__ float4 g_meta[NTOK];
__device__ int g_cnt[2][NEXP];
__device__ unsigned int g_etok[2][NEXP * NTOK];
__device__ float g_egat[2][NEXP * NTOK];

__device__ __forceinline__ uint32_t smem_u32(const void* p) {
    uint32_t a;
    asm("{ .reg .u64 t; cvta.to.shared.u64 t, %1; cvt.u32.u64 %0, t; }"
        : "=r"(a) : "l"(p));
    return a;
}

__device__ __forceinline__ uint32_t tf32rn(float f) {
    uint32_t r;
    asm("cvt.rna.tf32.f32 %0, %1;" : "=r"(r) : "f"(f));
    return r;
}

__device__ __forceinline__ uint32_t tf32rn_u(uint32_t f) {
    uint32_t r;
    asm("cvt.rna.tf32.f32 %0, %1;" : "=r"(r) : "r"(f));
    return r;
}

__device__ __forceinline__ void ldsm_x4(uint32_t& r0, uint32_t& r1,
                                        uint32_t& r2, uint32_t& r3, uint32_t a) {
    asm volatile("ldmatrix.sync.aligned.m8n8.x4.shared.b16 {%0,%1,%2,%3}, [%4];"
                 : "=r"(r0), "=r"(r1), "=r"(r2), "=r"(r3) : "r"(a));
}

__device__ __forceinline__ void mma_tf32(float* c,
                                         uint32_t a0, uint32_t a1, uint32_t a2,
                                         uint32_t a3, uint32_t b0, uint32_t b1) {
    asm volatile(
        "mma.sync.aligned.m16n8k8.row.col.f32.tf32.tf32.f32 "
        "{%0,%1,%2,%3}, {%4,%5,%6,%7}, {%8,%9}, {%0,%1,%2,%3};"
        : "+f"(c[0]), "+f"(c[1]), "+f"(c[2]), "+f"(c[3])
        : "r"(a0), "r"(a1), "r"(a2), "r"(a3), "r"(b0), "r"(b1));
}

__device__ __forceinline__ void cpa16(uint32_t dst, const void* src) {
    asm volatile("cp.async.cg.shared.global [%0], [%1], 16;"
                 :: "r"(dst), "l"(src) : "memory");
}

// ---------------- kernel 0: zero counters (graph replays!) ----------------
__global__ void k_zero() {
    if (threadIdx.x < 16) ((int*)g_cnt)[threadIdx.x] = 0;
}

// ---------------- kernel 1: gating + atomic slot allocation ----------------
#define G_SX   0
#define G_SWG  (128 * 132 * 4)
#define G_SMEM (G_SWG + HDIM * NEXP * 4)

extern __shared__ char smraw[];

__global__ void __launch_bounds__(128)
k_gate(const float* __restrict__ x, const float* __restrict__ wg) {
    float* sx  = (float*)(smraw + G_SX);
    float* swg = (float*)(smraw + G_SWG);
    __shared__ int wh0[4][8], wh1[4][8];
    __shared__ int gb0[8], gb1[8];

    const int tid = threadIdx.x, lane = tid & 31, w = tid >> 5;
    const int blk = blockIdx.x, tok0 = blk * 128;

    for (int i = tid; i < HDIM * NEXP; i += 128) swg[i] = wg[i];
    const float4* xg = (const float4*)(x + (size_t)tok0 * HDIM);
    for (int i = tid; i < 128 * 32; i += 128) {
        float4 v = xg[i];
        int t = i >> 5, c = (i & 31) * 4;
        *(float4*)(sx + t * 132 + c) = v;
    }
    __syncthreads();

    float lg[NEXP];
#pragma unroll
    for (int e = 0; e < NEXP; e++) lg[e] = 0.f;
    const float* xr = sx + tid * 132;
#pragma unroll 4
    for (int h4 = 0; h4 < 32; h4++) {
        float4 xq = *(const float4*)(xr + h4 * 4);
        const float* wr = swg + h4 * 32;
#pragma unroll
        for (int j = 0; j < 4; j++) {
            float xv = (j == 0) ? xq.x : (j == 1) ? xq.y : (j == 2) ? xq.z : xq.w;
            float4 wa = *(const float4*)(wr + j * 8);
            float4 wb = *(const float4*)(wr + j * 8 + 4);
            lg[0] = fmaf(xv, wa.x, lg[0]); lg[1] = fmaf(xv, wa.y, lg[1]);
            lg[2] = fmaf(xv, wa.z, lg[2]); lg[3] = fmaf(xv, wa.w, lg[3]);
            lg[4] = fmaf(xv, wb.x, lg[4]); lg[5] = fmaf(xv, wb.y, lg[5]);
            lg[6] = fmaf(xv, wb.z, lg[6]); lg[7] = fmaf(xv, wb.w, lg[7]);
        }
    }
    int i0 = 0; float v0 = lg[0];
#pragma unroll
    for (int e = 1; e < NEXP; e++)
        if (lg[e] > v0) { v0 = lg[e]; i0 = e; }
    int i1 = -1; float v1 = -3.4e38f;
#pragma unroll
    for (int e = 0; e < NEXP; e++)
        if (e != i0 && lg[e] > v1) { v1 = lg[e]; i1 = e; }
    float e1 = expf(v1 - v0);
    float g0 = 1.f / (1.f + e1);
    float g1 = e1 * g0;

    unsigned ltm = (1u << lane) - 1u;
    int myr0 = 0, myr1 = 0;
#pragma unroll
    for (int e = 0; e < NEXP; e++) {
        unsigned m0 = __ballot_sync(0xffffffffu, i0 == e);
        unsigned m1 = __ballot_sync(0xffffffffu, i1 == e);
        if (i0 == e) myr0 = __popc(m0 & ltm);
        if (i1 == e) myr1 = __popc(m1 & ltm);
        if (lane == e) { wh0[w][e] = __popc(m0); wh1[w][e] = __popc(m1); }
    }
    __syncthreads();
    int r0 = myr0, r1 = myr1;
    for (int ww = 0; ww < w; ww++) { r0 += wh0[ww][i0]; r1 += wh1[ww][i1]; }

    if (tid < NEXP) {
        int c0 = wh0[0][tid] + wh0[1][tid] + wh0[2][tid] + wh0[3][tid];
        int c1 = wh1[0][tid] + wh1[1][tid] + wh1[2][tid] + wh1[3][tid];
        gb0[tid] = atomicAdd(&g_cnt[0][tid], c0);
        gb1[tid] = atomicAdd(&g_cnt[1][tid], c1);
    }
    __syncthreads();

    int token = tok0 + tid;
    int s0 = gb0[i0] + r0, s1 = gb1[i1] + r1;
    g_etok[0][i0 * NTOK + s0] = (unsigned)token;
    g_egat[0][i0 * NTOK + s0] = g0;
    g_etok[1][i1 * NTOK + s1] = (unsigned)token;
    g_egat[1][i1 * NTOK + s1] = g1;
    g_meta[token] = make_float4(
        __uint_as_float((unsigned)i0 | ((unsigned)i1 << 8)), g0, g1, 0.f);
}

// ---------------- kernel 2: TF32 FFN GEMM ----------------
// smem: W^T [o=128][132f] | A0 [128][132f] | A1 | bias | tok/gate/meta x2
#define F_WT    0
#define F_A0    67584
#define F_A1    135168
#define F_BIAS  202752
#define F_TOK   206848      // 2 x 128 int
#define F_SGT   207872      // 2 x 128 float
#define F_META  208896      // 2 x 128 float4
#define F_SMEM  212992
#define NTHR_F 512

#define TILE_ELI(t, e_, li_) do { \
        e_ = 0; \
        _Pragma("unroll") \
        for (int k_ = 0; k_ < NEXP; k_++) if (tb[k_ + 1] <= (t)) e_ = k_ + 1; \
        li_ = (t) - tb[e_]; \
    } while (0)

__global__ void __launch_bounds__(NTHR_F, 1)
k_ffn(const float* __restrict__ x, const float* __restrict__ we,
      const float* __restrict__ be, float* __restrict__ out, int p) {
    const int tid = threadIdx.x, lane = tid & 31, w = tid >> 5;
    float* sbias = (float*)(smraw + F_BIAS);
    int* stok = (int*)(smraw + F_TOK);
    float* sgt = (float*)(smraw + F_SGT);
    float4* smeta = (float4*)(smraw + F_META);
    const uint32_t su = smem_u32(smraw);

    const unsigned* tokl = g_etok[p];
    const float* gatel   = g_egat[p];

    int cnt[NEXP], tb[NEXP + 1];
    tb[0] = 0;
#pragma unroll
    for (int e = 0; e < NEXP; e++) {
        cnt[e] = g_cnt[p][e];
        tb[e + 1] = tb[e] + ((cnt[e] + 127) >> 7);
    }
    const int ntiles = tb[NEXP];
    const int t0 = (int)((long long)blockIdx.x * ntiles / GRID3);
    const int t1 = (int)((long long)(blockIdx.x + 1) * ntiles / GRID3);
    if (t0 >= t1) return;

    for (int i = tid; i < NEXP * ODIM; i += NTHR_F) sbias[i] = be[i];

    // warp job: rows [mt*32,+32), cols [nq*32,+32)
    const int mt = w >> 2, nq = w & 3;
    const uint32_t a_loff = (uint32_t)(mt * 32 + (lane & 7) + ((lane >> 3) & 1) * 8)
                          * (FPITCH * 4) + (uint32_t)(lane >> 4) * 16u;
    const uint32_t b_loff = su + F_WT
                          + (uint32_t)(nq * 32 + (lane & 7)) * (FPITCH * 4)
                          + (uint32_t)(lane >> 3) * 16u;

    const int row = tid >> 2, q = tid & 3;
    const uint32_t a_dst = (uint32_t)row * (FPITCH * 4) + (uint32_t)q * 128u;

    // prologue: token/gate(t0), cp.async A(t0) raw x -> buf0
    unsigned nx_token; float nx_gate;
    {
        int e_, li_;
        TILE_ELI(t0, e_, li_);
        int lb = e_ * NTOK + li_ * 128;
        int v0 = min(128, cnt[e_] - li_ * 128);
        nx_token = 0; nx_gate = 0.f;
        if (row < v0) { nx_token = tokl[lb + row]; nx_gate = gatel[lb + row]; }
        const char* src = (const char*)(x + (size_t)nx_token * HDIM + q * 32);
#pragma unroll
        for (int i = 0; i < 8; i++)
            cpa16(su + F_A0 + a_dst + i * 16, src + i * 16);
        asm volatile("cp.async.commit_group;" ::: "memory");
    }

    int cur_e = -1;
    for (int t = t0; t < t1; t++) {
        const int cb = (t - t0) & 1;
        int e, li;
        TILE_ELI(t, e, li);
        const int valid = min(128, cnt[e] - li * 128);
        const unsigned token = nx_token;
        const float gv = nx_gate;

        if (t + 1 < t1) {
            int en, lin;
            TILE_ELI(t + 1, en, lin);
            int lbn = en * NTOK + lin * 128;
            int vn = min(128, cnt[en] - lin * 128);
            nx_token = 0; nx_gate = 0.f;
            if (row < vn) { nx_token = tokl[lbn + row]; nx_gate = gatel[lbn + row]; }
        }

        __syncthreads();   // GEMM(t-1) done: other A buf + W writable

        // stage W^T tf32-rounded on expert change (transpose via regs)
        if (e != cur_e) {
            const float* wsrc = we + (size_t)e * HDIM * ODIM;
#pragma unroll
            for (int i2 = 0; i2 < 32; i2++) {
                int i = tid + i2 * NTHR_F;       // i = h*128 + o
                int h = i >> 7, o = i & 127;
                ((uint32_t*)smraw)[o * FPITCH + h] = tf32rn(wsrc[i]);
            }
            cur_e = e;
        }

        // prefetch A(t+1) into other buffer
        if (t + 1 < t1) {
            const uint32_t abuf = cb ? F_A0 : F_A1;
            const char* src = (const char*)(x + (size_t)nx_token * HDIM + q * 32);
#pragma unroll
            for (int i = 0; i < 8; i++)
                cpa16(su + abuf + a_dst + i * 16, src + i * 16);
        }
        asm volatile("cp.async.commit_group;" ::: "memory");

        if (q == 0) {
            stok[cb * 128 + row] = (int)token;
            sgt[cb * 128 + row] = gv;
            if (p == 0) smeta[cb * 128 + row] = g_meta[token];
        }
        asm volatile("cp.async.wait_group 1;" ::: "memory");   // A(t) arrived
        __syncthreads();   // A(t) + W + tok visible

        // GEMM: 2 m16 x 4 n8 x 16 k8, TF32; A fragments rounded in regs
        const uint32_t a_base = su + (cb ? F_A1 : F_A0) + a_loff;
        float acc[2][4][4];
#pragma unroll
        for (int m = 0; m < 2; m++)
#pragma unroll
            for (int nt = 0; nt < 4; nt++)
#pragma unroll
                for (int j = 0; j < 4; j++) acc[m][nt][j] = 0.f;

#pragma unroll
        for (int k2 = 0; k2 < 8; k2++) {       // k16 steps
            uint32_t a8[2][2][4];              // [m16][k8][4]
#pragma unroll
            for (int m = 0; m < 2; m++) {
                uint32_t ab = a_base + (uint32_t)m * 16 * (FPITCH * 4)
                            + (uint32_t)k2 * 64;
                ldsm_x4(a8[m][0][0], a8[m][0][1], a8[m][0][2], a8[m][0][3], ab);
                ldsm_x4(a8[m][1][0], a8[m][1][1], a8[m][1][2], a8[m][1][3],
                        ab + 32);
                // round raw fp32 -> tf32 (RNA) on registers
#pragma unroll
                for (int kb = 0; kb < 2; kb++)
#pragma unroll
                    for (int j = 0; j < 4; j++)
                        a8[m][kb][j] = tf32rn_u(a8[m][kb][j]);
            }
            uint32_t bbv[4][4];                // [n8][b0lo,b1lo,b0hi,b1hi]
#pragma unroll
            for (int nt = 0; nt < 4; nt++) {
                uint32_t bb = b_loff + (uint32_t)nt * 8 * (FPITCH * 4)
                            + (uint32_t)k2 * 64;
                ldsm_x4(bbv[nt][0], bbv[nt][1], bbv[nt][2], bbv[nt][3], bb);
            }
#pragma unroll
            for (int kb = 0; kb < 2; kb++)
#pragma unroll
                for (int nt = 0; nt < 4; nt++)
#pragma unroll
                    for (int m = 0; m < 2; m++)
                        mma_tf32(acc[m][nt],
                                 a8[m][kb][0], a8[m][kb][1],
                                 a8[m][kb][2], a8[m][kb][3],
                                 bbv[nt][kb * 2], bbv[nt][kb * 2 + 1]);
        }

        // epilogue: gate applied here
        const int qr = lane >> 2, qk = (lane & 3) * 2;
#pragma unroll
        for (int m = 0; m < 2; m++) {
            int ra = mt * 32 + m * 16 + qr;
            int rb = ra + 8;
            bool va = ra < valid, vb = rb < valid;
            float* opa = va ? out + (size_t)stok[cb * 128 + ra] * ODIM : 0;
            float* opb = vb ? out + (size_t)stok[cb * 128 + rb] * ODIM : 0;
            float ga = va ? sgt[cb * 128 + ra] : 0.f;
            float gb = vb ? sgt[cb * 128 + rb] : 0.f;
            if (p == 0) {
#pragma unroll
                for (int hrow = 0; hrow < 2; hrow++) {
                    int r = hrow ? rb : ra;
                    float* op = hrow ? opb : opa;
                    float g = hrow ? gb : ga;
                    if (!(hrow ? vb : va)) continue;
                    float4 mm = smeta[cb * 128 + r];
                    unsigned u = __float_as_uint(mm.x);
                    const float* b0p = sbias + (u & 0xff) * ODIM;
                    const float* b1p = sbias + ((u >> 8) & 0xff) * ODIM;
                    float gg0 = mm.y, gg1 = mm.z;
                    const int ci = hrow * 2;
#pragma unroll
                    for (int nt = 0; nt < 4; nt++) {
                        int col = nq * 32 + nt * 8 + qk;
                        float2 v;
                        v.x = g * acc[m][nt][ci]
                            + gg0 * b0p[col] + gg1 * b1p[col];
                        v.y = g * acc[m][nt][ci + 1]
                            + gg0 * b0p[col + 1] + gg1 * b1p[col + 1];
                        *(float2*)(op + col) = v;
                    }
                }
            } else {
                float2 o[2][4];
#pragma unroll
                for (int nt = 0; nt < 4; nt++) {
                    int col = nq * 32 + nt * 8 + qk;
                    if (va) o[0][nt] = *(float2*)(opa + col);
                    if (vb) o[1][nt] = *(float2*)(opb + col);
                }
#pragma unroll
                for (int nt = 0; nt < 4; nt++) {
                    int col = nq * 32 + nt * 8 + qk;
                    if (va) {
                        float2 v = o[0][nt];
                        v.x += ga * acc[m][nt][0];
                        v.y += ga * acc[m][nt][1];
                        *(float2*)(opa + col) = v;
                    }
                    if (vb) {
                        float2 v = o[1][nt];
                        v.x += gb * acc[m][nt][2];
                        v.y += gb * acc[m][nt][3];
                        *(float2*)(opb + col) = v;
                    }
                }
            }
        }
    }
}

// ---------------- launch ----------------
extern "C" void kernel_launch(void* const* d_in, const int* in_sizes, int n_in,
                              void* d_out, int out_size) {
    const float* x  = (const float*)d_in[0];
    const float* wg = (const float*)d_in[1];
    // d_in[2] = w_noise (inactive in eval mode)
    const float* we = (const float*)d_in[3];
    const float* be = (const float*)d_in[4];
    float* out = (float*)d_out;

    cudaFuncSetAttribute(k_gate, cudaFuncAttributeMaxDynamicSharedMemorySize,
                         G_SMEM);
    cudaFuncSetAttribute(k_ffn, cudaFuncAttributeMaxDynamicSharedMemorySize,
                         F_SMEM);

    k_zero<<<1, 32>>>();
    k_gate<<<NBLK, 128, G_SMEM>>>(x, wg);
    k_ffn<<<GRID3, NTHR_F, F_SMEM>>>(x, we, be, out, 0);
    k_ffn<<<GRID3, NTHR_F, F_SMEM>>>(x, we, be, out, 1);
}